// round 7
// baseline (speedup 1.0000x reference)
#include <cuda_runtime.h>
#include <math.h>

#define NB 2
#define CH 128
#define NP 256
#define SS 240
#define MM 20
#define KXN 40
#define NPIX (SS*SS)
#define NPOS (NB*NPIX)

// ---- scratch (device globals; no allocation allowed) ----
__device__ float  g_hA[NB*CH*NP*NP];
__device__ float  g_hB[NB*CH*NP*NP];
__device__ float2 g_Gy [NB*CH*NP*MM];
__device__ float2 g_Fm [NB*CH*KXN*MM];
__device__ float2 g_Fo [NB*CH*KXN*MM];
__device__ float2 g_Gy2[NB*CH*NP*MM];
__device__ float  g_feat[NPOS*CH];
__device__ float2 g_csy [NP*MM];     // (cos,sin)(2*pi*ky*y/256), y-major
__device__ float2 g_csx [NP*KXN];    // (cos,sin)(2*pi*kx*x/256), x-major
__device__ float2 g_csyT[MM*NP];     // same as csy, ky-major (coalesced in y)

__device__ __forceinline__ float gelu_f(float v){
    return 0.5f*v*(1.0f+erff(v*0.70710678118654752f));
}

// ---- twiddle tables (exact: sincospif of integer/128) ----
__global__ void k_tables(){
    int i = blockIdx.x*blockDim.x + threadIdx.x;
    if (i < NP*MM){
        int y=i/MM, ky=i%MM; float s,c;
        sincospif((float)(ky*y)*(1.0f/128.0f), &s, &c);
        g_csy[i]=make_float2(c,s);
    } else if (i < NP*MM + NP*KXN){
        int j=i-NP*MM; int xx=j/KXN, kxi=j%KXN;
        int kx = (kxi<MM)? kxi : 236+(kxi-MM);
        float s,c; sincospif((float)(kx*xx)*(1.0f/128.0f), &s, &c);
        g_csx[j]=make_float2(c,s);
    } else if (i < 2*NP*MM + NP*KXN){
        int j=i-(NP*MM+NP*KXN); int ky=j/NP, y=j%NP;
        float s,c; sincospif((float)(ky*y)*(1.0f/128.0f), &s, &c);
        g_csyT[j]=make_float2(c,s);
    }
}

// ---- fc0 + grid channels, write padded (b,c,x,y) into g_hA ----
__global__ void k_fc0(const float* __restrict__ x, const float* __restrict__ w,
                      const float* __restrict__ b){
    __shared__ float ws[5][CH];
    __shared__ float bs[CH];
    int t=threadIdx.x;
    for(int i=t;i<5*CH;i+=256) ws[i/CH][i%CH]=w[i];
    for(int i=t;i<CH;i+=256) bs[i]=b[i];
    __syncthreads();
    int xr=blockIdx.x, bb=blockIdx.y, y=t;
    bool inside=(xr<SS)&&(y<SS);
    float v0=0.f,v1=0.f,v2=0.f,v3=0.f,v4=0.f;
    if(inside){
        const float* xp=x+(((size_t)bb*SS+xr)*SS+y)*3;
        v0=xp[0]; v1=xp[1]; v2=xp[2];
        v3=(float)xr*(1.0f/239.0f);
        v4=(float)y *(1.0f/239.0f);
    }
    float* op=g_hA+(((size_t)bb*CH)*NP+xr)*NP+y;
    for(int c=0;c<CH;c++){
        float a=0.f;
        if(inside){
            a=bs[c];
            a=fmaf(v0,ws[0][c],a); a=fmaf(v1,ws[1][c],a); a=fmaf(v2,ws[2][c],a);
            a=fmaf(v3,ws[3][c],a); a=fmaf(v4,ws[4][c],a);
        }
        op[(size_t)c*NP*NP]=a;
    }
}

// ---- forward y-DFT: h(row,y) -> Gy(row,ky), 32 rows/block, 2 rows/thread ----
__global__ void __launch_bounds__(320) k_dfty(int pp){
    __shared__ float hs[32*NP];
    const float* h = pp ? g_hB : g_hA;
    int t=threadIdx.x;
    size_t rowbase=(size_t)blockIdx.x*32;
    const float* hp=h+rowbase*NP;
    for(int i=t;i<32*NP;i+=320) hs[i]=hp[i];
    __syncthreads();
    int ky=t%MM, rl=t/MM;                 // rl 0..15, 2 rows each
    const float* h0=hs+(2*rl)*NP;
    const float* h1=h0+NP;
    float a0r=0.f,a0i=0.f,a1r=0.f,a1i=0.f;
    #pragma unroll 4
    for(int y=0;y<NP;y++){
        float2 w=g_csy[y*MM+ky];
        float u0=h0[y], u1=h1[y];
        a0r=fmaf(u0,w.x,a0r); a0i=fmaf(u0,w.y,a0i);
        a1r=fmaf(u1,w.x,a1r); a1i=fmaf(u1,w.y,a1i);
    }
    g_Gy[(rowbase+2*rl  )*MM+ky]=make_float2(a0r,-a0i);
    g_Gy[(rowbase+2*rl+1)*MM+ky]=make_float2(a1r,-a1i);
}

// ---- forward x-DFT: Gy(x,ky) -> Fm(kxi,ky), one (b,c) per block ----
__global__ void __launch_bounds__(800) k_dftx(){
    __shared__ float2 gsh[NP*MM];
    int bc=blockIdx.x, t=threadIdx.x;
    const float2* gp=g_Gy+(size_t)bc*NP*MM;
    for(int i=t;i<NP*MM;i+=800) gsh[i]=gp[i];
    __syncthreads();
    int kxi=t%KXN, ky=t/KXN;
    float ar=0.f, ai=0.f;
    #pragma unroll 4
    for(int xx=0;xx<NP;xx++){
        float2 w=g_csx[xx*KXN+kxi];
        float2 f=gsh[xx*MM+ky];
        ar += f.x*w.x + f.y*w.y;          // F = sum G * e^{-i th}
        ai += f.y*w.x - f.x*w.y;
    }
    g_Fm[((size_t)bc*KXN+kxi)*MM+ky]=make_float2(ar,ai);
}

// ---- mode mixing: Fo[b,o,p] = sum_i Fm[b,i,p]*W[i,o,p] ----
__global__ void __launch_bounds__(1024) k_mix(const float* __restrict__ w1,
                                              const float* __restrict__ w2, int l){
    __shared__ float2 fsh[2][CH][4];
    int kxi=blockIdx.x, myg=blockIdx.y, t=threadIdx.x;
    {
        int b=t>>9, rem=t&511, i=rem>>2, myl=rem&3;
        fsh[b][i][myl]=g_Fm[(((size_t)(b*CH+i))*KXN+kxi)*MM + myg*4+myl];
    }
    __syncthreads();
    int myl=t&3, b=(t>>2)&1, o=t>>3;
    int my=myg*4+myl;
    int mx=(kxi<MM)? kxi : (kxi-MM);
    const float2* wp=(const float2*)((kxi<MM)? w1 : w2);
    size_t base=(((size_t)l*CH*CH + o)*MM + mx)*MM + my;       // i=0 term
    float ar=0.f, ai=0.f;
    #pragma unroll 4
    for(int i=0;i<CH;i++){
        float2 wv=wp[base+(size_t)i*CH*MM*MM];
        float2 f=fsh[b][i][myl];
        ar += f.x*wv.x - f.y*wv.y;
        ai += f.x*wv.y + f.y*wv.x;
    }
    g_Fo[(((size_t)(b*CH+o))*KXN+kxi)*MM+my]=make_float2(ar,ai);
}

// ---- inverse x-DFT: Fo(kxi,ky) -> Gy2(x,ky), pre-scaled ----
__global__ void __launch_bounds__(512) k_idftx(){
    __shared__ float2 fsh[KXN*MM];
    int bo=blockIdx.x, t=threadIdx.x;
    const float2* fp=g_Fo+(size_t)bo*KXN*MM;
    for(int i=t;i<KXN*MM;i+=512) fsh[i]=fp[i];
    __syncthreads();
    int xx=t&255, kg=t>>8;               // kg 0..1, 10 ky each
    float ar[10], ai[10];
    #pragma unroll
    for(int j=0;j<10;j++){ ar[j]=0.f; ai[j]=0.f; }
    for(int k=0;k<KXN;k++){
        float2 w=g_csx[xx*KXN+k];
        #pragma unroll
        for(int j=0;j<10;j++){
            float2 f=fsh[k*MM+kg*10+j];
            ar[j] += f.x*w.x - f.y*w.y;  // G2 = sum F * e^{+i th}
            ai[j] += f.x*w.y + f.y*w.x;
        }
    }
    float2* op=g_Gy2+((size_t)bo*NP+xx)*MM;
    #pragma unroll
    for(int j=0;j<10;j++){
        int ky=kg*10+j;
        float fk=((ky==0)?1.0f:2.0f)*(1.0f/65536.0f);
        op[ky]=make_float2(ar[j]*fk, ai[j]*fk);
    }
}

// ---- inverse y-DFT (real part): write spectral term s into dst ----
__global__ void __launch_bounds__(256) k_idfty(int pp){
    __shared__ float2 rsh[32*MM];
    float* dst = pp ? g_hA : g_hB;
    int t=threadIdx.x;
    size_t rowbase=(size_t)blockIdx.x*32;
    const float2* gp=g_Gy2+rowbase*MM;
    for(int i=t;i<32*MM;i+=256) rsh[i]=gp[i];
    float cy[MM], sy[MM];
    #pragma unroll
    for(int ky=0;ky<MM;ky++){ float2 w=g_csyT[ky*NP+t]; cy[ky]=w.x; sy[ky]=w.y; }
    __syncthreads();
    for(int r=0;r<32;r++){
        float a=0.f;
        #pragma unroll
        for(int ky=0;ky<MM;ky++){
            float2 f=rsh[r*MM+ky];
            a=fmaf(f.x,cy[ky],a);
            a=fmaf(-f.y,sy[ky],a);
        }
        dst[(rowbase+r)*NP+t]=a;
    }
}

// ---- 1x1 conv GEMM + spectral + bias (+gelu): dst = act(dst + W@src + b) ----
__global__ void __launch_bounds__(256) k_lin(int pp, const float* __restrict__ ww,
                                             const float* __restrict__ wb, int l, int dogelu){
    const float* src = pp ? g_hB : g_hA;
    float*       dst = pp ? g_hA : g_hB;
    __shared__ float As[16][64];
    __shared__ float Bs[16][64];
    int t=threadIdx.x;
    int tile=blockIdx.x;
    int x=tile>>2, ybase=(tile&3)<<6;
    int obase=blockIdx.y<<6, bb=blockIdx.z;
    const float* W = ww + (size_t)l*CH*CH;
    int lo=t&63, kq=t>>6;
    const float* srow = src + (((size_t)bb*CH)*NP + x)*NP + ybase;
    float acc[4][4];                      // [oj][yi]
    #pragma unroll
    for(int i=0;i<4;i++){ acc[i][0]=0.f; acc[i][1]=0.f; acc[i][2]=0.f; acc[i][3]=0.f; }
    int ty=t&15, to=t>>4;
    for(int c0=0;c0<CH;c0+=16){
        float4 w4 = *(const float4*)(W + (size_t)(obase+lo)*CH + c0 + kq*4);
        As[kq*4+0][lo]=w4.x; As[kq*4+1][lo]=w4.y; As[kq*4+2][lo]=w4.z; As[kq*4+3][lo]=w4.w;
        #pragma unroll
        for(int q=0;q<4;q++){
            int kk=kq*4+q;
            Bs[kk][lo]=srow[(size_t)(c0+kk)*NP*NP + lo];
        }
        __syncthreads();
        #pragma unroll
        for(int kk=0;kk<16;kk++){
            float4 a =*(const float4*)&As[kk][to*4];
            float4 bv=*(const float4*)&Bs[kk][ty*4];
            float av[4]={a.x,a.y,a.z,a.w};
            float bvv[4]={bv.x,bv.y,bv.z,bv.w};
            #pragma unroll
            for(int oj=0;oj<4;oj++)
                #pragma unroll
                for(int yi=0;yi<4;yi++)
                    acc[oj][yi]=fmaf(av[oj],bvv[yi],acc[oj][yi]);
        }
        __syncthreads();
    }
    #pragma unroll
    for(int oj=0;oj<4;oj++){
        int o=obase+to*4+oj;
        float bias=wb[l*CH+o];
        float* dp=dst+(((size_t)(bb*CH+o))*NP+x)*NP+ybase+ty*4;
        float4 s4=*(const float4*)dp;
        float v0=acc[oj][0]+s4.x+bias;
        float v1=acc[oj][1]+s4.y+bias;
        float v2=acc[oj][2]+s4.z+bias;
        float v3=acc[oj][3]+s4.w+bias;
        if(dogelu){ v0=gelu_f(v0); v1=gelu_f(v1); v2=gelu_f(v2); v3=gelu_f(v3); }
        float4 o4=make_float4(v0,v1,v2,v3);
        *(float4*)dp=o4;
    }
}

// ---- crop + fc1 + gelu -> g_feat (p-major, c contiguous) ----
__global__ void __launch_bounds__(256) k_fc1(const float* __restrict__ w,
                                             const float* __restrict__ b){
    __shared__ float As[16][64];
    __shared__ float Bs[16][64];
    int t=threadIdx.x;
    int pbase=blockIdx.x*64, obase=blockIdx.y<<6;
    int lo=t&63, kq=t>>6;
    int p=pbase+lo;
    int bb=p/NPIX; int rem=p-bb*NPIX;
    int xr=rem/SS;  int yr=rem-xr*SS;
    size_t base=(size_t)bb*CH*NP*NP + (size_t)xr*NP + yr;
    float acc[4][4];                      // [pi][oj]
    #pragma unroll
    for(int i=0;i<4;i++){ acc[i][0]=0.f; acc[i][1]=0.f; acc[i][2]=0.f; acc[i][3]=0.f; }
    int tp=t&15, to=t>>4;
    for(int c0=0;c0<CH;c0+=16){
        #pragma unroll
        for(int q=0;q<4;q++){
            int kk=kq*4+q;
            As[kk][lo]=w[(size_t)(c0+kk)*CH + obase+lo];
            Bs[kk][lo]=g_hB[base + (size_t)(c0+kk)*NP*NP];
        }
        __syncthreads();
        #pragma unroll
        for(int kk=0;kk<16;kk++){
            float4 a =*(const float4*)&As[kk][to*4];
            float4 bv=*(const float4*)&Bs[kk][tp*4];
            float av[4]={a.x,a.y,a.z,a.w};
            float bvv[4]={bv.x,bv.y,bv.z,bv.w};
            #pragma unroll
            for(int pi=0;pi<4;pi++)
                #pragma unroll
                for(int oj=0;oj<4;oj++)
                    acc[pi][oj]=fmaf(bvv[pi],av[oj],acc[pi][oj]);
        }
        __syncthreads();
    }
    #pragma unroll
    for(int pi=0;pi<4;pi++){
        float* fp=g_feat+(size_t)(pbase+tp*4+pi)*CH + obase+to*4;
        float4 o4;
        o4.x=gelu_f(acc[pi][0]+b[obase+to*4+0]);
        o4.y=gelu_f(acc[pi][1]+b[obase+to*4+1]);
        o4.z=gelu_f(acc[pi][2]+b[obase+to*4+2]);
        o4.w=gelu_f(acc[pi][3]+b[obase+to*4+3]);
        *(float4*)fp=o4;
    }
}

// ---- 4 heads: gelu(feat@W1k+b1)@W2k + b2 -> out ----
__global__ void __launch_bounds__(256) k_heads(const float* __restrict__ w1,
                                               const float* __restrict__ b1,
                                               const float* __restrict__ w2,
                                               const float* __restrict__ b2,
                                               float* __restrict__ out){
    __shared__ float Fs[32][65];
    __shared__ float Ws[32][64];
    __shared__ float red[64][17];
    int t=threadIdx.x;
    int pbase=blockIdx.x*64;
    int tp=t&15, td=t>>4;
    for(int k=0;k<4;k++){
        float acc[4][4];                  // [pi][dj]
        #pragma unroll
        for(int i=0;i<4;i++){ acc[i][0]=0.f; acc[i][1]=0.f; acc[i][2]=0.f; acc[i][3]=0.f; }
        for(int c0=0;c0<CH;c0+=32){
            for(int i=t;i<2048;i+=256){
                int r=i>>6, cc=i&63;
                Ws[r][cc]=w1[(size_t)k*CH*64 + (size_t)(c0+r)*64 + cc];
            }
            for(int i=t;i<2048;i+=256){
                int c=i&31, pl=i>>5;
                Fs[c][pl]=g_feat[(size_t)(pbase+pl)*CH + c0 + c];
            }
            __syncthreads();
            #pragma unroll 8
            for(int kk=0;kk<32;kk++){
                float4 a=*(const float4*)&Ws[kk][td*4];
                float av[4]={a.x,a.y,a.z,a.w};
                float f0=Fs[kk][tp*4+0], f1=Fs[kk][tp*4+1];
                float f2=Fs[kk][tp*4+2], f3=Fs[kk][tp*4+3];
                #pragma unroll
                for(int dj=0;dj<4;dj++){
                    acc[0][dj]=fmaf(f0,av[dj],acc[0][dj]);
                    acc[1][dj]=fmaf(f1,av[dj],acc[1][dj]);
                    acc[2][dj]=fmaf(f2,av[dj],acc[2][dj]);
                    acc[3][dj]=fmaf(f3,av[dj],acc[3][dj]);
                }
            }
            __syncthreads();
        }
        #pragma unroll
        for(int pi=0;pi<4;pi++){
            float v=0.f;
            #pragma unroll
            for(int dj=0;dj<4;dj++){
                int d=td*4+dj;
                float h1=gelu_f(acc[pi][dj]+b1[k*64+d]);
                v=fmaf(h1, w2[k*64+d], v);
            }
            red[tp*4+pi][td]=v;
        }
        __syncthreads();
        if(t<64){
            float v=b2[k];
            #pragma unroll
            for(int j=0;j<16;j++) v+=red[t][j];
            out[(size_t)k*NPOS + pbase + t]=v;
        }
        __syncthreads();
    }
}

extern "C" void kernel_launch(void* const* d_in, const int* in_sizes, int n_in,
                              void* d_out, int out_size){
    (void)in_sizes; (void)n_in; (void)out_size;
    const float* x     =(const float*)d_in[0];
    const float* fc0_w =(const float*)d_in[1];
    const float* fc0_b =(const float*)d_in[2];
    const float* sw1   =(const float*)d_in[3];
    const float* sw2   =(const float*)d_in[4];
    const float* w_w   =(const float*)d_in[5];
    const float* w_b   =(const float*)d_in[6];
    const float* fc1_w =(const float*)d_in[7];
    const float* fc1_b =(const float*)d_in[8];
    const float* h1w   =(const float*)d_in[9];
    const float* h1b   =(const float*)d_in[10];
    const float* h2w   =(const float*)d_in[11];
    const float* h2b   =(const float*)d_in[12];
    float* out=(float*)d_out;

    k_tables<<<80,256>>>();
    k_fc0<<<dim3(NP,NB),256>>>(x,fc0_w,fc0_b);
    for(int l=0;l<5;l++){
        int pp=l&1;
        k_dfty <<<NB*CH*NP/32,320>>>(pp);
        k_dftx <<<NB*CH,800>>>();
        k_mix  <<<dim3(KXN,5),1024>>>(sw1,sw2,l);
        k_idftx<<<NB*CH,512>>>();
        k_idfty<<<NB*CH*NP/32,256>>>(pp);
        k_lin  <<<dim3(NP*NP/64,2,NB),256>>>(pp,w_w,w_b,l,(l<4)?1:0);
    }
    k_fc1  <<<dim3(NPOS/64,2),256>>>(fc1_w,fc1_b);
    k_heads<<<NPOS/64,256>>>(h1w,h1b,h2w,h2b,out);
}